// round 1
// baseline (speedup 1.0000x reference)
#include <cuda_runtime.h>
#include <cuda_bf16.h>
#include <math.h>

// Problem constants
#define BB 2
#define NQ 900
#define CC 256
#define HH 8
#define NN 4096
#define DH 32
#define HID 512

// -------- scratch (device globals; no allocation allowed) --------
__device__ float g_q [BB*NQ*CC];     // scaled Q projection
__device__ float g_k [BB*NN*CC];
__device__ float g_v [BB*NN*CC];
__device__ float g_kt[BB*HH*DH*NN];  // [bh][d][n]
__device__ float g_vt[BB*HH*DH*NN];
__device__ float g_rx[BB*NQ*64*HH];
__device__ float g_ry[BB*NQ*64*HH];
__device__ float g_ao[BB*NQ*CC];     // attention out pre-projection

// =====================================================================
// Generic GEMM: out[M,256] = A[M,256] @ W[256,256]; out = (acc+bias)*scale
// BM=64, BN=64, BK=16; 256 threads; 4x4 per thread.
// =====================================================================
__global__ __launch_bounds__(256) void gemm256_kernel(
    const float* __restrict__ A, const float* __restrict__ W,
    const float* __restrict__ bias, float* __restrict__ out,
    int M, float scale)
{
    __shared__ float As[16][64];
    __shared__ float Ws[16][64];
    const int tid = threadIdx.x;
    const int tx = tid & 15, ty = tid >> 4;
    const int bm = blockIdx.y * 64, bn = blockIdx.x * 64;

    float acc[4][4] = {};

    for (int kt = 0; kt < 256; kt += 16) {
        // A tile: 64 rows x 16 cols -> As[k][m]
        {
            int r = tid >> 2, c4 = (tid & 3) * 4;
            int row = bm + r;
            float4 v = (row < M) ? *(const float4*)&A[row*256 + kt + c4]
                                 : make_float4(0.f,0.f,0.f,0.f);
            As[c4+0][r] = v.x; As[c4+1][r] = v.y; As[c4+2][r] = v.z; As[c4+3][r] = v.w;
        }
        // W tile: 16 rows x 64 cols
        {
            int r = tid >> 4, c4 = (tid & 15) * 4;
            *(float4*)&Ws[r][c4] = *(const float4*)&W[(kt + r)*256 + bn + c4];
        }
        __syncthreads();
        #pragma unroll
        for (int k = 0; k < 16; k++) {
            float4 a4 = *(const float4*)&As[k][ty*4];
            float4 b4 = *(const float4*)&Ws[k][tx*4];
            float a[4] = {a4.x, a4.y, a4.z, a4.w};
            float b[4] = {b4.x, b4.y, b4.z, b4.w};
            #pragma unroll
            for (int i = 0; i < 4; i++)
                #pragma unroll
                for (int j = 0; j < 4; j++)
                    acc[i][j] += a[i] * b[j];
        }
        __syncthreads();
    }
    float4 bv = *(const float4*)&bias[bn + tx*4];
    float bb[4] = {bv.x, bv.y, bv.z, bv.w};
    #pragma unroll
    for (int i = 0; i < 4; i++) {
        int row = bm + ty*4 + i;
        if (row < M) {
            float4 o;
            o.x = (acc[i][0] + bb[0]) * scale;
            o.y = (acc[i][1] + bb[1]) * scale;
            o.z = (acc[i][2] + bb[2]) * scale;
            o.w = (acc[i][3] + bb[3]) * scale;
            *(float4*)&out[row*256 + bn + tx*4] = o;
        }
    }
}

// =====================================================================
// Transpose K/V projections: in[(b*N+n)*C + h*32 + d] -> out[bh*32*N + d*N + n]
// =====================================================================
__global__ __launch_bounds__(256) void transpose_kernel(
    const float* __restrict__ in, float* __restrict__ out)
{
    __shared__ float t[32][33];
    const int bh = blockIdx.y;
    const int b = bh >> 3, h = bh & 7;
    const int n0 = blockIdx.x * 32;
    const int tx = threadIdx.x, ty = threadIdx.y; // 32 x 8
    #pragma unroll
    for (int i = 0; i < 4; i++) {
        int n = n0 + ty + i*8;
        t[ty + i*8][tx] = in[(b*NN + n)*CC + h*32 + tx];
    }
    __syncthreads();
    #pragma unroll
    for (int i = 0; i < 4; i++) {
        int d = ty + i*8;
        out[((size_t)bh*32 + d)*NN + n0 + tx] = t[tx][d];
    }
}

// =====================================================================
// RPE MLP: one CTA per (b,q). rows 0..63 -> x-axis pos, 64..127 -> y-axis.
// hidden_j = relu(d0*W1[0,j] + d1*W1[1,j] + b1[j]);  out[h] = sum_j hidden_j*W2[j,h]
// =====================================================================
__global__ __launch_bounds__(256) void rpe_kernel(
    const float* __restrict__ ref,
    const float* __restrict__ W1x, const float* __restrict__ b1x, const float* __restrict__ W2x,
    const float* __restrict__ W1y, const float* __restrict__ b1y, const float* __restrict__ W2y,
    float* __restrict__ rx, float* __restrict__ ry)
{
    __shared__ float sW1[2][1024];
    __shared__ float sb1[2][512];
    __shared__ float sW2[2][4096];
    const int bq = blockIdx.x;
    const int tid = threadIdx.x;

    for (int i = tid; i < 1024; i += 256) { sW1[0][i] = W1x[i]; sW1[1][i] = W1y[i]; }
    for (int i = tid; i < 512;  i += 256) { sb1[0][i] = b1x[i]; sb1[1][i] = b1y[i]; }
    for (int i = tid; i < 4096; i += 256) { sW2[0][i] = W2x[i]; sW2[1][i] = W2y[i]; }
    float4 box = *(const float4*)&ref[bq*4];   // cx, cy, w, h
    __syncthreads();

    const int w = tid >> 5, lane = tid & 31;
    const int axis = w >> 2;
    const float lo = (axis == 0) ? box.x - box.z*0.5f : box.y - box.w*0.5f;
    const float hi = (axis == 0) ? box.x + box.z*0.5f : box.y + box.w*0.5f;
    const float* w1 = sW1[axis];
    const float* b1 = sb1[axis];
    const float* w2 = sW2[axis];
    float* outp = (axis == 0) ? rx : ry;
    const int pos0 = (w & 3) * 16;

    for (int g = 0; g < 2; g++) {
        float d0[8], d1[8];
        #pragma unroll
        for (int r = 0; r < 8; r++) {
            float p = ((float)(pos0 + g*8 + r) + 0.5f) * 16.0f;
            d0[r] = lo - p;
            d1[r] = hi - p;
        }
        float acc[8][8];
        #pragma unroll
        for (int r = 0; r < 8; r++)
            #pragma unroll
            for (int h = 0; h < 8; h++) acc[r][h] = 0.f;

        for (int jj = 0; jj < 16; jj++) {
            int j = jj*32 + lane;
            float u = w1[j], v = w1[512 + j], bb = b1[j];
            float w2v[8];
            #pragma unroll
            for (int h = 0; h < 8; h++) w2v[h] = w2[j*8 + h];
            #pragma unroll
            for (int r = 0; r < 8; r++) {
                float hv = fmaxf(d0[r]*u + d1[r]*v + bb, 0.f);
                #pragma unroll
                for (int h = 0; h < 8; h++) acc[r][h] += hv * w2v[h];
            }
        }
        #pragma unroll
        for (int r = 0; r < 8; r++) {
            #pragma unroll
            for (int h = 0; h < 8; h++) {
                float v = acc[r][h];
                #pragma unroll
                for (int o = 16; o; o >>= 1) v += __shfl_xor_sync(0xffffffffu, v, o);
                if (lane == h)
                    outp[(bq*64 + pos0 + g*8 + r)*8 + h] = v;
            }
        }
    }
}

// =====================================================================
// Fused attention (flash-style online softmax).
// Grid: (ceil(NQ/8), B*H). Block: 128 threads = 4 warps, 2 queries/warp.
// Each lane owns 4 consecutive keys per 128-key tile (float4 K/V loads).
// =====================================================================
__global__ __launch_bounds__(128) void attn_kernel(
    const float* __restrict__ qp, const float* __restrict__ kt,
    const float* __restrict__ vt, const float* __restrict__ rx,
    const float* __restrict__ ry, const unsigned char* __restrict__ mask,
    float* __restrict__ ao)
{
    __shared__ float Ks[32][128];
    __shared__ float Vs[32][128];
    __shared__ float rxs[8][64], rys[8][64];
    __shared__ float madd[128];

    const int tid = threadIdx.x;
    const int w = tid >> 5, lane = tid & 31;
    const int bh = blockIdx.y, b = bh >> 3, h = bh & 7;
    const int base_q = blockIdx.x * 8;
    const int qA = base_q + w, qB = base_q + w + 4;
    const bool vA = (qA < NQ), vB = (qB < NQ);
    const int qAc = vA ? qA : (NQ - 1);
    const int qBc = vB ? qB : (NQ - 1);

    float qra[32], qrb[32];
    {
        const float* pa = qp + (b*NQ + qAc)*CC + h*32;
        const float* pb = qp + (b*NQ + qBc)*CC + h*32;
        #pragma unroll
        for (int d = 0; d < 32; d++) { qra[d] = pa[d]; qrb[d] = pb[d]; }
    }
    for (int i = lane; i < 64; i += 32) {
        rxs[w][i]     = rx[((b*NQ + qAc)*64 + i)*8 + h];
        rys[w][i]     = ry[((b*NQ + qAc)*64 + i)*8 + h];
        rxs[w + 4][i] = rx[((b*NQ + qBc)*64 + i)*8 + h];
        rys[w + 4][i] = ry[((b*NQ + qBc)*64 + i)*8 + h];
    }

    const float* ktp = kt + (size_t)bh*32*NN;
    const float* vtp = vt + (size_t)bh*32*NN;

    float mA = -3.4e38f, lA = 0.f, mB = -3.4e38f, lB = 0.f;
    float accA[32], accB[32];
    #pragma unroll
    for (int d = 0; d < 32; d++) { accA[d] = 0.f; accB[d] = 0.f; }

    for (int t = 0; t < 32; t++) {
        __syncthreads();
        const int base = t * 128;
        #pragma unroll
        for (int r = 0; r < 8; r++) {
            int lin = tid + r*128;             // 0..1023
            int d = lin >> 5, i4 = (lin & 31) * 4;
            *(float4*)&Ks[d][i4] = *(const float4*)&ktp[d*NN + base + i4];
            *(float4*)&Vs[d][i4] = *(const float4*)&vtp[d*NN + base + i4];
        }
        if (tid < 128) madd[tid] = mask[b*NN + base + tid] ? -100.f : 0.f;
        __syncthreads();

        float sA[4], sB[4];
        #pragma unroll
        for (int c = 0; c < 4; c++) {
            int kl = lane*4 + c, kk = base + kl;
            float ma = madd[kl];
            sA[c] = ma + rxs[w][kk & 63]     + rys[w][kk >> 6];
            sB[c] = ma + rxs[w + 4][kk & 63] + rys[w + 4][kk >> 6];
        }
        #pragma unroll
        for (int d = 0; d < 32; d++) {
            float4 kv = *(const float4*)&Ks[d][lane*4];
            float a = qra[d], bq2 = qrb[d];
            sA[0] += a*kv.x; sA[1] += a*kv.y; sA[2] += a*kv.z; sA[3] += a*kv.w;
            sB[0] += bq2*kv.x; sB[1] += bq2*kv.y; sB[2] += bq2*kv.z; sB[3] += bq2*kv.w;
        }
        // online softmax update (per-tile rescale)
        float mxA = fmaxf(fmaxf(sA[0], sA[1]), fmaxf(sA[2], sA[3]));
        float mxB = fmaxf(fmaxf(sB[0], sB[1]), fmaxf(sB[2], sB[3]));
        float mnA = fmaxf(mA, mxA), mnB = fmaxf(mB, mxB);
        float cA = __expf(mA - mnA), cB = __expf(mB - mnB);
        mA = mnA; mB = mnB;
        float pA[4], pB[4];
        lA *= cA; lB *= cB;
        #pragma unroll
        for (int c = 0; c < 4; c++) {
            pA[c] = __expf(sA[c] - mnA); lA += pA[c];
            pB[c] = __expf(sB[c] - mnB); lB += pB[c];
        }
        #pragma unroll
        for (int d = 0; d < 32; d++) {
            float4 vv = *(const float4*)&Vs[d][lane*4];
            accA[d] = accA[d]*cA + pA[0]*vv.x + pA[1]*vv.y + pA[2]*vv.z + pA[3]*vv.w;
            accB[d] = accB[d]*cB + pB[0]*vv.x + pB[1]*vv.y + pB[2]*vv.z + pB[3]*vv.w;
        }
    }

    // cross-lane merge, query A
    {
        float ml = mA;
        #pragma unroll
        for (int o = 16; o; o >>= 1) mA = fmaxf(mA, __shfl_xor_sync(0xffffffffu, mA, o));
        float corr = __expf(ml - mA);
        lA *= corr;
        #pragma unroll
        for (int o = 16; o; o >>= 1) lA += __shfl_xor_sync(0xffffffffu, lA, o);
        float keep = 0.f;
        #pragma unroll
        for (int d = 0; d < 32; d++) {
            float v = accA[d] * corr;
            #pragma unroll
            for (int o = 16; o; o >>= 1) v += __shfl_xor_sync(0xffffffffu, v, o);
            if (lane == d) keep = v;
        }
        if (vA) ao[(b*NQ + qA)*CC + h*32 + lane] = keep / lA;
    }
    // cross-lane merge, query B
    {
        float ml = mB;
        #pragma unroll
        for (int o = 16; o; o >>= 1) mB = fmaxf(mB, __shfl_xor_sync(0xffffffffu, mB, o));
        float corr = __expf(ml - mB);
        lB *= corr;
        #pragma unroll
        for (int o = 16; o; o >>= 1) lB += __shfl_xor_sync(0xffffffffu, lB, o);
        float keep = 0.f;
        #pragma unroll
        for (int d = 0; d < 32; d++) {
            float v = accB[d] * corr;
            #pragma unroll
            for (int o = 16; o; o >>= 1) v += __shfl_xor_sync(0xffffffffu, v, o);
            if (lane == d) keep = v;
        }
        if (vB) ao[(b*NQ + qB)*CC + h*32 + lane] = keep / lB;
    }
}

// =====================================================================
// Launch
// =====================================================================
extern "C" void kernel_launch(void* const* d_in, const int* in_sizes, int n_in,
                              void* d_out, int out_size)
{
    const float* query = (const float*)d_in[1];
    const float* ref   = (const float*)d_in[2];
    const float* kin   = (const float*)d_in[3];
    const float* vin   = (const float*)d_in[4];
    const unsigned char* mask = (const unsigned char*)d_in[6];
    const float* W1x = (const float*)d_in[7];
    const float* b1x = (const float*)d_in[8];
    const float* W2x = (const float*)d_in[9];
    const float* W1y = (const float*)d_in[10];
    const float* b1y = (const float*)d_in[11];
    const float* W2y = (const float*)d_in[12];
    const float* Wq  = (const float*)d_in[13];
    const float* bq  = (const float*)d_in[14];
    const float* Wk  = (const float*)d_in[15];
    const float* bk  = (const float*)d_in[16];
    const float* Wv  = (const float*)d_in[17];
    const float* bv  = (const float*)d_in[18];
    const float* Wp  = (const float*)d_in[19];
    const float* bp  = (const float*)d_in[20];
    float* out = (float*)d_out;

    void *pq, *pk, *pv, *pkt, *pvt, *prx, *pry, *pao;
    cudaGetSymbolAddress(&pq,  g_q);
    cudaGetSymbolAddress(&pk,  g_k);
    cudaGetSymbolAddress(&pv,  g_v);
    cudaGetSymbolAddress(&pkt, g_kt);
    cudaGetSymbolAddress(&pvt, g_vt);
    cudaGetSymbolAddress(&prx, g_rx);
    cudaGetSymbolAddress(&pry, g_ry);
    cudaGetSymbolAddress(&pao, g_ao);

    const float scale = 0.17677669529663687f; // 32^-0.5
    const int MQ = BB * NQ;   // 1800
    const int MK = BB * NN;   // 8192

    gemm256_kernel<<<dim3(4, (MQ + 63)/64), 256>>>(query, Wq, bq, (float*)pq, MQ, scale);
    gemm256_kernel<<<dim3(4, MK/64), 256>>>(kin, Wk, bk, (float*)pk, MK, 1.0f);
    gemm256_kernel<<<dim3(4, MK/64), 256>>>(vin, Wv, bv, (float*)pv, MK, 1.0f);

    transpose_kernel<<<dim3(NN/32, BB*HH), dim3(32,8)>>>((const float*)pk, (float*)pkt);
    transpose_kernel<<<dim3(NN/32, BB*HH), dim3(32,8)>>>((const float*)pv, (float*)pvt);

    rpe_kernel<<<MQ, 256>>>(ref, W1x, b1x, W2x, W1y, b1y, W2y, (float*)prx, (float*)pry);

    attn_kernel<<<dim3((NQ + 7)/8, BB*HH), 128>>>(
        (const float*)pq, (const float*)pkt, (const float*)pvt,
        (const float*)prx, (const float*)pry, mask, (float*)pao);

    gemm256_kernel<<<dim3(4, (MQ + 63)/64), 256>>>((const float*)pao, Wp, bp, out, MQ, 1.0f);
}